// round 5
// baseline (speedup 1.0000x reference)
#include <cuda_runtime.h>
#include <cuda_bf16.h>
#include <cstdint>

// ---------------- problem constants ----------------
#define B_    8
#define NTOK  4096
#define C_    768
#define H_    12
#define D_    64
#define M_    (B_ * NTOK)     // 32768
#define QKVN  (3 * C_)        // 2304
#define KDIM  768

// ---------------- scratch (device globals) ----------------
__device__ float g_phiq[(size_t)B_ * H_ * NTOK * D_];
__device__ float g_phik[(size_t)B_ * H_ * NTOK * D_];
__device__ float g_v   [(size_t)B_ * H_ * NTOK * D_];
__device__ float g_kv  [B_ * H_ * D_ * D_];
__device__ float g_ksum[B_ * H_ * D_];
__device__ float g_attn[(size_t)M_ * C_];

__device__ __nv_bfloat16 g_xhi[(size_t)M_ * KDIM];
__device__ __nv_bfloat16 g_xlo[(size_t)M_ * KDIM];
__device__ __nv_bfloat16 g_whi[(size_t)QKVN * KDIM];
__device__ __nv_bfloat16 g_wlo[(size_t)QKVN * KDIM];
__device__ __nv_bfloat16 g_pwhi[(size_t)C_ * KDIM];
__device__ __nv_bfloat16 g_pwlo[(size_t)C_ * KDIM];
__device__ __nv_bfloat16 g_lhi[(size_t)M_ * KDIM];
__device__ __nv_bfloat16 g_llo[(size_t)M_ * KDIM];

// ---------------- low-level helpers ----------------
__device__ __forceinline__ uint32_t smem_to_u32(const void* p) {
    uint32_t a;
    asm("{ .reg .u64 t; cvta.to.shared.u64 t, %1; cvt.u32.u64 %0, t; }"
        : "=r"(a) : "l"(p));
    return a;
}

#define CP_ASYNC_CG(dst, src) \
    asm volatile("cp.async.cg.shared.global [%0], [%1], 16;" :: "r"(dst), "l"(src))
#define CP_COMMIT()  asm volatile("cp.async.commit_group;" ::: "memory")
#define CP_WAIT(N)   asm volatile("cp.async.wait_group %0;" :: "n"(N) : "memory")

#define LDMATRIX_X4(r0, r1, r2, r3, addr) \
    asm volatile("ldmatrix.sync.aligned.m8n8.x4.shared.b16 {%0,%1,%2,%3}, [%4];" \
        : "=r"(r0), "=r"(r1), "=r"(r2), "=r"(r3) : "r"(addr))
#define LDMATRIX_X2(r0, r1, addr) \
    asm volatile("ldmatrix.sync.aligned.m8n8.x2.shared.b16 {%0,%1}, [%2];" \
        : "=r"(r0), "=r"(r1) : "r"(addr))

#define MMA_BF16(d, a, b) \
    asm volatile("mma.sync.aligned.m16n8k16.row.col.f32.bf16.bf16.f32 " \
        "{%0,%1,%2,%3}, {%4,%5,%6,%7}, {%8,%9}, {%0,%1,%2,%3};" \
        : "+f"((d)[0]), "+f"((d)[1]), "+f"((d)[2]), "+f"((d)[3]) \
        : "r"((a)[0]), "r"((a)[1]), "r"((a)[2]), "r"((a)[3]), \
          "r"((b)[0]), "r"((b)[1]))

// ---------------- GEMM tiling ----------------
#define BM 128
#define BN 192
#define GT 384                   // 12 warps (3 per SMSP)
#define BKB 32                   // bf16 k-elems per stage
#define KB  (KDIM / BKB)         // 24 k-blocks
#define ROWB 80                  // padded row stride in bytes
#define A_ARR (128 * ROWB)       // 10240
#define B_ARR (192 * ROWB)       // 15360
#define AHI_OFF 0
#define ALO_OFF A_ARR
#define BHI_OFF (2 * A_ARR)
#define BLO_OFF (2 * A_ARR + B_ARR)
#define STAGE (2 * A_ARR + 2 * B_ARR)   // 51200
#define NSTG 4
#define SMEM_GEMM (NSTG * STAGE)        // 204800
#define NCHUNK 2560              // 16B chunks per stage

// 4-stage cp.async mainloop; warp tile 64x32; acc[4][4][4] fp32; 3-term split.
__device__ __forceinline__ void gemm_mainloop(
    const __nv_bfloat16* __restrict__ Ahi, const __nv_bfloat16* __restrict__ Alo,
    const __nv_bfloat16* __restrict__ Bhi, const __nv_bfloat16* __restrict__ Blo,
    int bm, int bn, uint32_t sb, int tid, int wid, int lane,
    float acc[4][4][4])
{
    const int wm = (wid & 1) * 64;
    const int wn = (wid >> 1) * 32;

    const uint32_t a_row  = (uint32_t)(wm + (lane & 7) + ((lane >> 3) & 1) * 8);
    const uint32_t a_colb = (uint32_t)(((lane >> 4) & 1) * 16);
    const uint32_t b_row  = (uint32_t)(wn + (lane & 7));
    const uint32_t b_colb = (uint32_t)(((lane >> 3) & 1) * 16);

    #pragma unroll
    for (int i = 0; i < 4; i++)
        #pragma unroll
        for (int j = 0; j < 4; j++)
            #pragma unroll
            for (int r = 0; r < 4; r++) acc[i][j][r] = 0.f;

    // copy one k-block's operands into stage slot
    auto fill = [&](int kb, int slot) {
        const int k0 = kb * BKB;
        const uint32_t so = sb + (uint32_t)(slot * STAGE);
        for (int idx = tid; idx < NCHUNK; idx += GT) {
            const __nv_bfloat16* src;
            uint32_t dst;
            if (idx < 1024) {                       // A hi/lo: 512 chunks each
                int arr = idx >> 9;
                int r   = (idx >> 2) & 127;
                int ch  = idx & 3;
                src = (arr ? Alo : Ahi) + (size_t)(bm + r) * KDIM + k0 + ch * 8;
                dst = so + arr * A_ARR + r * ROWB + ch * 16;
            } else {                                // B hi/lo: 768 chunks each
                int t   = idx - 1024;
                int arr = t >= 768;
                int u   = arr ? t - 768 : t;
                int r   = u >> 2;
                int ch  = u & 3;
                src = (arr ? Blo : Bhi) + (size_t)(bn + r) * KDIM + k0 + ch * 8;
                dst = so + BHI_OFF + arr * B_ARR + r * ROWB + ch * 16;
            }
            CP_ASYNC_CG(dst, src);
        }
    };

    // preload stages 0,1
    fill(0, 0); CP_COMMIT();
    fill(1, 1); CP_COMMIT();

    for (int kb = 0; kb < KB; kb++) {
        const int pf = kb + 2;
        if (pf < KB) fill(pf, pf & (NSTG - 1));
        CP_COMMIT();
        CP_WAIT(2);
        __syncthreads();

        const uint32_t st = sb + (uint32_t)((kb & (NSTG - 1)) * STAGE);
        #pragma unroll
        for (int ks = 0; ks < 2; ks++) {
            const uint32_t kB = (uint32_t)(ks * 32);
            uint32_t afh[4][4], afl[4][4], bfh[4][2], bfl[4][2];
            #pragma unroll
            for (int mt = 0; mt < 4; mt++) {
                uint32_t ao = st + (a_row + mt * 16) * ROWB + kB + a_colb;
                LDMATRIX_X4(afh[mt][0], afh[mt][1], afh[mt][2], afh[mt][3], ao);
                LDMATRIX_X4(afl[mt][0], afl[mt][1], afl[mt][2], afl[mt][3], ao + A_ARR);
            }
            #pragma unroll
            for (int nt = 0; nt < 4; nt++) {
                uint32_t bo = st + BHI_OFF + (b_row + nt * 8) * ROWB + kB + b_colb;
                LDMATRIX_X2(bfh[nt][0], bfh[nt][1], bo);
                LDMATRIX_X2(bfl[nt][0], bfl[nt][1], bo + B_ARR);
            }
            #pragma unroll
            for (int mt = 0; mt < 4; mt++)
                #pragma unroll
                for (int nt = 0; nt < 4; nt++) {
                    MMA_BF16(acc[mt][nt], afh[mt], bfh[nt]);
                    MMA_BF16(acc[mt][nt], afh[mt], bfl[nt]);
                    MMA_BF16(acc[mt][nt], afl[mt], bfh[nt]);
                }
        }
    }
}

// ---------------- GEMM1: qkv with fused bias+rope+softmax+scatter ----------
#define EPS 196   // epi row stride (floats), 192 + 4 pad

__global__ __launch_bounds__(GT, 1)
void mma_gemm_qkv(const __nv_bfloat16* __restrict__ Ahi, const __nv_bfloat16* __restrict__ Alo,
                  const __nv_bfloat16* __restrict__ Bhi, const __nv_bfloat16* __restrict__ Blo,
                  const float* __restrict__ rope,
                  const float* __restrict__ q_bias, const float* __restrict__ v_bias,
                  float* __restrict__ phiq, float* __restrict__ phik, float* __restrict__ vout)
{
    extern __shared__ char smem[];
    const uint32_t sb = smem_to_u32(smem);
    const int tid = threadIdx.x, wid = tid >> 5, lane = tid & 31;
    const int bm = blockIdx.y * BM, bn = blockIdx.x * BN;

    float acc[4][4][4];
    gemm_mainloop(Ahi, Alo, Bhi, Blo, bm, bn, sb, tid, wid, lane, acc);
    __syncthreads();

    // dump accumulators to smem (128 x 192, stride 196)
    float* epi = (float*)smem;
    const int wm = (wid & 1) * 64, wn = (wid >> 1) * 32;
    const int er = lane >> 2, ec = (lane & 3) * 2;
    #pragma unroll
    for (int mt = 0; mt < 4; mt++)
        #pragma unroll
        for (int nt = 0; nt < 4; nt++) {
            int r0 = wm + mt * 16 + er, c = wn + nt * 8 + ec;
            *(float2*)&epi[r0 * EPS + c]       = make_float2(acc[mt][nt][0], acc[mt][nt][1]);
            *(float2*)&epi[(r0 + 8) * EPS + c] = make_float2(acc[mt][nt][2], acc[mt][nt][3]);
        }
    __syncthreads();

    // fused epilogue: 8-lane group = one (row, head)
    const int region = bn / C_;            // 0=q, 1=k, 2=v (tiles never straddle: 768%192==0)
    const int col0   = bn - region * C_;   // offset within region (mult of 192)
    const float* bias = (region == 0) ? q_bias : (region == 2 ? v_bias : nullptr);
    float* outbuf = (region == 0) ? phiq : (region == 1 ? phik : vout);
    const int h0 = col0 >> 6;              // first head in tile (3 heads per tile)

    const int dof = (lane & 7) << 3;       // d offset within head (0..56)

    #pragma unroll 2
    for (int rr = 0; rr < 8; rr++) {
        const int G    = rr * 48 + (tid >> 3);  // group 0..383
        const int row  = G / 3;
        const int head = G - row * 3;
        const int gtok = bm + row;
        const int b    = gtok >> 12;
        const int n    = gtok & (NTOK - 1);

        float4 v0 = *(float4*)&epi[row * EPS + head * 64 + dof];
        float4 v1 = *(float4*)&epi[row * EPS + head * 64 + dof + 4];
        float vals[8] = { v0.x, v0.y, v0.z, v0.w, v1.x, v1.y, v1.z, v1.w };

        if (bias) {
            const float* bp = bias + col0 + head * 64 + dof;
            #pragma unroll
            for (int j = 0; j < 8; j++) vals[j] += bp[j];
        }

        if (region != 2) {
            if (n >= 1) {
                const float* rp = rope + (size_t)(n - 1) * (2 * D_) + dof;
                float4 s0 = *(const float4*)rp;
                float4 s1 = *(const float4*)(rp + 4);
                float4 c0 = *(const float4*)(rp + 64);
                float4 c1 = *(const float4*)(rp + 68);
                float snv[8] = { s0.x, s0.y, s0.z, s0.w, s1.x, s1.y, s1.z, s1.w };
                float csv[8] = { c0.x, c0.y, c0.z, c0.w, c1.x, c1.y, c1.z, c1.w };
                #pragma unroll
                for (int p = 0; p < 4; p++) {
                    float t0 = vals[2 * p], t1 = vals[2 * p + 1];
                    vals[2 * p]     = t0 * csv[2 * p]     - t1 * snv[2 * p];
                    vals[2 * p + 1] = t1 * csv[2 * p + 1] + t0 * snv[2 * p + 1];
                }
            }
            // softmax over the 8-lane head group
            float m = vals[0];
            #pragma unroll
            for (int j = 1; j < 8; j++) m = fmaxf(m, vals[j]);
            #pragma unroll
            for (int o = 1; o < 8; o <<= 1)
                m = fmaxf(m, __shfl_xor_sync(0xffffffffu, m, o));
            float s = 0.f;
            #pragma unroll
            for (int j = 0; j < 8; j++) { vals[j] = expf(vals[j] - m); s += vals[j]; }
            #pragma unroll
            for (int o = 1; o < 8; o <<= 1)
                s += __shfl_xor_sync(0xffffffffu, s, o);
            float rs = 1.f / s;
            #pragma unroll
            for (int j = 0; j < 8; j++) vals[j] *= rs;
        }

        float* dst = outbuf + (((size_t)b * H_ + h0 + head) * NTOK + n) * D_ + dof;
        *(float4*)dst       = make_float4(vals[0], vals[1], vals[2], vals[3]);
        *(float4*)(dst + 4) = make_float4(vals[4], vals[5], vals[6], vals[7]);
    }
}

// ---------------- GEMM2: proj with bias ----------------
__global__ __launch_bounds__(GT, 1)
void mma_gemm_proj(const __nv_bfloat16* __restrict__ Ahi, const __nv_bfloat16* __restrict__ Alo,
                   const __nv_bfloat16* __restrict__ Bhi, const __nv_bfloat16* __restrict__ Blo,
                   float* __restrict__ Cc, int N, const float* __restrict__ bias_full)
{
    extern __shared__ char smem[];
    const uint32_t sb = smem_to_u32(smem);
    const int tid = threadIdx.x, wid = tid >> 5, lane = tid & 31;
    const int bm = blockIdx.y * BM, bn = blockIdx.x * BN;

    float acc[4][4][4];
    gemm_mainloop(Ahi, Alo, Bhi, Blo, bm, bn, sb, tid, wid, lane, acc);

    const int wm = (wid & 1) * 64, wn = (wid >> 1) * 32;
    const int er = lane >> 2, ec = (lane & 3) * 2;
    #pragma unroll
    for (int mt = 0; mt < 4; mt++) {
        #pragma unroll
        for (int nt = 0; nt < 4; nt++) {
            int row = bm + wm + mt * 16 + er;
            int col = bn + wn + nt * 8 + ec;
            float b0 = bias_full[col], b1 = bias_full[col + 1];
            *(float2*)(Cc + (size_t)row * N + col) =
                make_float2(acc[mt][nt][0] + b0, acc[mt][nt][1] + b1);
            *(float2*)(Cc + (size_t)(row + 8) * N + col) =
                make_float2(acc[mt][nt][2] + b0, acc[mt][nt][3] + b1);
        }
    }
}

// ---------------- fp32 -> bf16 hi/lo split ----------------
__global__ void cvt_split(const float* __restrict__ x,
                          __nv_bfloat16* __restrict__ hi,
                          __nv_bfloat16* __restrict__ lo, int n4)
{
    int i = blockIdx.x * blockDim.x + threadIdx.x;
    if (i >= n4) return;
    float4 f = ((const float4*)x)[i];
    __nv_bfloat16 h[4], l[4];
    #pragma unroll
    for (int j = 0; j < 4; j++) {
        float fv = ((const float*)&f)[j];
        h[j] = __float2bfloat16(fv);
        l[j] = __float2bfloat16(fv - __bfloat162float(h[j]));
    }
    ((uint2*)hi)[i] = *(uint2*)h;
    ((uint2*)lo)[i] = *(uint2*)l;
}

// ---------------- zero helper ------------------------------------------------
__global__ void zero_kernel(float* __restrict__ p, int n)
{
    int i = blockIdx.x * blockDim.x + threadIdx.x;
    if (i < n) p[i] = 0.f;
}

// ---------------- kv + ksum reduction ----------------------------------------
#define KV_SPLIT 8
__global__ void kv_kernel(const float* __restrict__ phik,
                          const float* __restrict__ v,
                          float* __restrict__ kv,
                          float* __restrict__ ksum)
{
    int bh  = blockIdx.x;
    int seg = blockIdx.y;
    int tid = threadIdx.x;

    const float* pk = phik + (size_t)bh * NTOK * D_;
    const float* pv = v    + (size_t)bh * NTOK * D_;
    int n0 = seg * (NTOK / KV_SPLIT);

    __shared__ float sk[16][64];
    __shared__ float sv[16][64];

    int td = (tid >> 4) << 2;
    int te = (tid & 15) << 2;
    int r  = tid >> 4;
    int c4 = (tid & 15) << 2;

    float acc[4][4];
#pragma unroll
    for (int i = 0; i < 4; i++)
#pragma unroll
        for (int j = 0; j < 4; j++) acc[i][j] = 0.f;
    float ksl = 0.f;

    for (int nc = n0; nc < n0 + NTOK / KV_SPLIT; nc += 16) {
        *(float4*)&sk[r][c4] = *(const float4*)(pk + (size_t)(nc + r) * D_ + c4);
        *(float4*)&sv[r][c4] = *(const float4*)(pv + (size_t)(nc + r) * D_ + c4);
        __syncthreads();
#pragma unroll
        for (int nn = 0; nn < 16; nn++) {
            float a[4], b[4];
            *(float4*)a = *(const float4*)&sk[nn][td];
            *(float4*)b = *(const float4*)&sv[nn][te];
#pragma unroll
            for (int i = 0; i < 4; i++)
#pragma unroll
                for (int j = 0; j < 4; j++)
                    acc[i][j] = fmaf(a[i], b[j], acc[i][j]);
        }
        if (tid < D_) {
#pragma unroll
            for (int nn = 0; nn < 16; nn++) ksl += sk[nn][tid];
        }
        __syncthreads();
    }

    float* kvb = kv + (size_t)bh * D_ * D_;
#pragma unroll
    for (int i = 0; i < 4; i++)
#pragma unroll
        for (int j = 0; j < 4; j++)
            atomicAdd(&kvb[(td + i) * D_ + te + j], acc[i][j]);
    if (tid < D_) atomicAdd(&ksum[bh * D_ + tid], ksl);
}

// ---------------- attention output -------------------------------------------
__global__ void attn_out_kernel(const float* __restrict__ phiq,
                                const float* __restrict__ kv,
                                const float* __restrict__ ksum,
                                float* __restrict__ outp)
{
    int bh   = blockIdx.x;
    int tgrp = blockIdx.y;
    int tid  = threadIdx.x;

    __shared__ float skv[D_][D_];
    __shared__ float sks[D_];
    __shared__ float spq[8][D_];

    const float* kvb = kv + (size_t)bh * D_ * D_;
    for (int i = tid; i < D_ * D_ / 4; i += 256)
        ((float4*)skv)[i] = ((const float4*)kvb)[i];
    if (tid < D_) sks[tid] = ksum[bh * D_ + tid];
    __syncthreads();

    int warp = tid >> 5, lane = tid & 31;
    int n = tgrp * 8 + warp;

    const float* pq = phiq + ((size_t)bh * NTOK + n) * D_;
    float2 qp = ((const float2*)pq)[lane];
    spq[warp][2 * lane]     = qp.x;
    spq[warp][2 * lane + 1] = qp.y;
    __syncwarp();

    float z = qp.x * sks[2 * lane] + qp.y * sks[2 * lane + 1];
#pragma unroll
    for (int o = 16; o > 0; o >>= 1) z += __shfl_xor_sync(0xffffffffu, z, o);
    float rz = 1.f / (z + 1e-5f);

    float o0 = 0.f, o1 = 0.f;
#pragma unroll 16
    for (int d = 0; d < D_; d++) {
        float p = spq[warp][d];
        float2 kvp = ((const float2*)&skv[d][0])[lane];
        o0 = fmaf(p, kvp.x, o0);
        o1 = fmaf(p, kvp.y, o1);
    }

    int b = bh / H_, h = bh % H_;
    float* orow = outp + ((size_t)(b * NTOK + n)) * C_ + h * D_;
    ((float2*)orow)[lane] = make_float2(o0 * rz, o1 * rz);
}

// ---------------- layernorm -> split bf16 ------------------------------------
__global__ void ln_kernel(const float* __restrict__ x,
                          const float* __restrict__ g,
                          const float* __restrict__ b,
                          __nv_bfloat16* __restrict__ yhi,
                          __nv_bfloat16* __restrict__ ylo)
{
    int row = blockIdx.x;
    int tid = threadIdx.x; // 256
    const float* xr = x + (size_t)row * C_;

    float v0 = xr[tid], v1 = xr[tid + 256], v2 = xr[tid + 512];
    float s  = v0 + v1 + v2;
    float ss = v0 * v0 + v1 * v1 + v2 * v2;
#pragma unroll
    for (int o = 16; o > 0; o >>= 1) {
        s  += __shfl_xor_sync(0xffffffffu, s,  o);
        ss += __shfl_xor_sync(0xffffffffu, ss, o);
    }
    __shared__ float ws[8], wss[8];
    int warp = tid >> 5, lane = tid & 31;
    if (lane == 0) { ws[warp] = s; wss[warp] = ss; }
    __syncthreads();
    if (tid == 0) {
        float ts = 0.f, tss = 0.f;
#pragma unroll
        for (int i = 0; i < 8; i++) { ts += ws[i]; tss += wss[i]; }
        ws[0] = ts; wss[0] = tss;
    }
    __syncthreads();
    float mean = ws[0] * (1.f / C_);
    float var  = wss[0] * (1.f / C_) - mean * mean;
    float inv  = rsqrtf(var + 1e-5f);

    size_t rb = (size_t)row * C_;
#pragma unroll
    for (int j = 0; j < 3; j++) {
        int c = tid + j * 256;
        float vv = (j == 0 ? v0 : (j == 1 ? v1 : v2));
        float y = (vv - mean) * inv * g[c] + b[c];
        __nv_bfloat16 hh = __float2bfloat16(y);
        yhi[rb + c] = hh;
        ylo[rb + c] = __float2bfloat16(y - __bfloat162float(hh));
    }
}

// ---------------- launch ------------------------------------------------------
extern "C" void kernel_launch(void* const* d_in, const int* in_sizes, int n_in,
                              void* d_out, int out_size)
{
    (void)in_sizes; (void)n_in; (void)out_size;
    const float* x      = (const float*)d_in[0];
    const float* rope   = (const float*)d_in[1];
    const float* qkv_w  = (const float*)d_in[2];
    const float* q_bias = (const float*)d_in[3];
    const float* v_bias = (const float*)d_in[4];
    const float* norm_g = (const float*)d_in[5];
    const float* norm_b = (const float*)d_in[6];
    const float* proj_w = (const float*)d_in[7];
    const float* proj_b = (const float*)d_in[8];
    float* out = (float*)d_out;

    float *phiq, *phik, *v, *kv, *ksum, *attn;
    __nv_bfloat16 *xhi, *xlo, *whi, *wlo, *pwhi, *pwlo, *lhi, *llo;
    cudaGetSymbolAddress((void**)&phiq, g_phiq);
    cudaGetSymbolAddress((void**)&phik, g_phik);
    cudaGetSymbolAddress((void**)&v,    g_v);
    cudaGetSymbolAddress((void**)&kv,   g_kv);
    cudaGetSymbolAddress((void**)&ksum, g_ksum);
    cudaGetSymbolAddress((void**)&attn, g_attn);
    cudaGetSymbolAddress((void**)&xhi,  g_xhi);
    cudaGetSymbolAddress((void**)&xlo,  g_xlo);
    cudaGetSymbolAddress((void**)&whi,  g_whi);
    cudaGetSymbolAddress((void**)&wlo,  g_wlo);
    cudaGetSymbolAddress((void**)&pwhi, g_pwhi);
    cudaGetSymbolAddress((void**)&pwlo, g_pwlo);
    cudaGetSymbolAddress((void**)&lhi,  g_lhi);
    cudaGetSymbolAddress((void**)&llo,  g_llo);

    cudaFuncSetAttribute(mma_gemm_qkv,  cudaFuncAttributeMaxDynamicSharedMemorySize, SMEM_GEMM);
    cudaFuncSetAttribute(mma_gemm_proj, cudaFuncAttributeMaxDynamicSharedMemorySize, SMEM_GEMM);

    // 0) fp32 -> split bf16 conversions
    {
        int n4 = (M_ * KDIM) / 4;
        cvt_split<<<(n4 + 255) / 256, 256>>>(x, xhi, xlo, n4);
        n4 = (QKVN * KDIM) / 4;
        cvt_split<<<(n4 + 255) / 256, 256>>>(qkv_w, whi, wlo, n4);
        n4 = (C_ * KDIM) / 4;
        cvt_split<<<(n4 + 255) / 256, 256>>>(proj_w, pwhi, pwlo, n4);
    }

    // 1) fused qkv GEMM + bias + rope + softmax + head-scatter
    mma_gemm_qkv<<<dim3(QKVN / BN, M_ / BM), GT, SMEM_GEMM>>>(
        xhi, xlo, whi, wlo, rope, q_bias, v_bias, phiq, phik, v);

    // 2) zero accumulators
    zero_kernel<<<(B_ * H_ * D_ * D_ + 1023) / 1024, 1024>>>(kv, B_ * H_ * D_ * D_);
    zero_kernel<<<(B_ * H_ * D_ + 1023) / 1024, 1024>>>(ksum, B_ * H_ * D_);

    // 3) kv & ksum reductions
    kv_kernel<<<dim3(B_ * H_, KV_SPLIT), 256>>>(phik, v, kv, ksum);

    // 4) attention output
    attn_out_kernel<<<dim3(B_ * H_, NTOK / 8), 256>>>(phiq, kv, ksum, attn);

    // 5) layernorm (fused split-bf16 output)
    ln_kernel<<<M_, 256>>>(attn, norm_g, norm_b, lhi, llo);

    // 6) out = ln @ proj_w^T + proj_b
    mma_gemm_proj<<<dim3(C_ / BN, M_ / BM), GT, SMEM_GEMM>>>(
        lhi, llo, pwhi, pwlo, out, C_, proj_b);
}

// round 6
// speedup vs baseline: 1.2864x; 1.2864x over previous
#include <cuda_runtime.h>
#include <cuda_fp16.h>
#include <cstdint>

// ---------------- problem constants ----------------
#define B_    8
#define NTOK  4096
#define C_    768
#define H_    12
#define D_    64
#define M_    (B_ * NTOK)     // 32768
#define QKVN  (3 * C_)        // 2304
#define KDIM  768

// ---------------- scratch (device globals) ----------------
__device__ float g_phiq[(size_t)B_ * H_ * NTOK * D_];
__device__ float g_phik[(size_t)B_ * H_ * NTOK * D_];
__device__ float g_v   [(size_t)B_ * H_ * NTOK * D_];
__device__ float g_kv  [B_ * H_ * D_ * D_];
__device__ float g_ksum[B_ * H_ * D_];
__device__ float g_attn[(size_t)M_ * C_];

__device__ __half g_xhi[(size_t)M_ * KDIM];
__device__ __half g_xlo[(size_t)M_ * KDIM];
__device__ __half g_w  [(size_t)QKVN * KDIM];
__device__ __half g_pw [(size_t)C_ * KDIM];
__device__ __half g_lhi[(size_t)M_ * KDIM];
__device__ __half g_llo[(size_t)M_ * KDIM];

// ---------------- low-level helpers ----------------
__device__ __forceinline__ uint32_t smem_to_u32(const void* p) {
    uint32_t a;
    asm("{ .reg .u64 t; cvta.to.shared.u64 t, %1; cvt.u32.u64 %0, t; }"
        : "=r"(a) : "l"(p));
    return a;
}

#define CP_ASYNC_CG(dst, src) \
    asm volatile("cp.async.cg.shared.global [%0], [%1], 16;" :: "r"(dst), "l"(src))
#define CP_COMMIT()  asm volatile("cp.async.commit_group;" ::: "memory")
#define CP_WAIT(N)   asm volatile("cp.async.wait_group %0;" :: "n"(N) : "memory")

#define LDMATRIX_X4(r0, r1, r2, r3, addr) \
    asm volatile("ldmatrix.sync.aligned.m8n8.x4.shared.b16 {%0,%1,%2,%3}, [%4];" \
        : "=r"(r0), "=r"(r1), "=r"(r2), "=r"(r3) : "r"(addr))
#define LDMATRIX_X2(r0, r1, addr) \
    asm volatile("ldmatrix.sync.aligned.m8n8.x2.shared.b16 {%0,%1}, [%2];" \
        : "=r"(r0), "=r"(r1) : "r"(addr))

#define MMA_F16(d, a, b) \
    asm volatile("mma.sync.aligned.m16n8k16.row.col.f32.f16.f16.f32 " \
        "{%0,%1,%2,%3}, {%4,%5,%6,%7}, {%8,%9}, {%0,%1,%2,%3};" \
        : "+f"((d)[0]), "+f"((d)[1]), "+f"((d)[2]), "+f"((d)[3]) \
        : "r"((a)[0]), "r"((a)[1]), "r"((a)[2]), "r"((a)[3]), \
          "r"((b)[0]), "r"((b)[1]))

// ---------------- GEMM tiling (R4 geometry, 2-term fp16) ----------------
#define BM 128
#define BN 128
#define BKB 32                   // f16 k-elems per stage
#define KB  (KDIM / BKB)         // 24 k-blocks
#define ROWB 80                  // padded row stride in bytes
#define ARR_BYTES (128 * ROWB)   // 10240 per operand array
#define STAGE (3 * ARR_BYTES)    // Ahi, Alo, B = 30720
#define NSTG 4
#define SMEM_GEMM (NSTG * STAGE) // 122880

// 4-stage cp.async mainloop; warp tile 64x32; acc[4][4][4] fp32; 2-term fp16.
__device__ __forceinline__ void gemm_mainloop(
    const __half* __restrict__ Ahi, const __half* __restrict__ Alo,
    const __half* __restrict__ Bw,
    int bm, int bn, uint32_t sb, int tid, int wid, int lane,
    float acc[4][4][4])
{
    const int wm = (wid & 1) * 64;
    const int wn = (wid >> 1) * 32;

    // per-thread cp.async source/dest: 6 x 16B chunks per stage
    const int lrow = tid >> 2;           // 0..63
    const int lch  = tid & 3;            // chunk-in-row
    const __half* srcs[6];
    uint32_t dsts[6];
    {
        const __half* bases[3] = { Ahi, Alo, Bw };
        #pragma unroll
        for (int i = 0; i < 6; i++) {
            int arr = i >> 1;
            int row = (i & 1) * 64 + lrow;
            int roff = (arr < 2) ? (bm + row) : (bn + row);
            srcs[i] = bases[arr] + (size_t)roff * KDIM + lch * 8;
            dsts[i] = sb + arr * ARR_BYTES + row * ROWB + lch * 16;
        }
    }

    const uint32_t a_row  = (uint32_t)(wm + (lane & 7) + ((lane >> 3) & 1) * 8);
    const uint32_t a_colb = (uint32_t)(((lane >> 4) & 1) * 16);
    const uint32_t b_row  = (uint32_t)(wn + (lane & 7));
    const uint32_t b_colb = (uint32_t)(((lane >> 3) & 1) * 16);

    #pragma unroll
    for (int i = 0; i < 4; i++)
        #pragma unroll
        for (int j = 0; j < 4; j++)
            #pragma unroll
            for (int r = 0; r < 4; r++) acc[i][j][r] = 0.f;

    // preload stages 0,1
    #pragma unroll
    for (int p = 0; p < 2; p++) {
        const uint32_t so = (uint32_t)(p * STAGE);
        const int k0 = p * BKB;
        #pragma unroll
        for (int i = 0; i < 6; i++) CP_ASYNC_CG(dsts[i] + so, srcs[i] + k0);
        CP_COMMIT();
    }

    for (int kb = 0; kb < KB; kb++) {
        const int pf = kb + 2;
        if (pf < KB) {
            const uint32_t so = (uint32_t)((pf & (NSTG - 1)) * STAGE);
            const int k0 = pf * BKB;
            #pragma unroll
            for (int i = 0; i < 6; i++) CP_ASYNC_CG(dsts[i] + so, srcs[i] + k0);
        }
        CP_COMMIT();
        CP_WAIT(2);
        __syncthreads();

        const uint32_t st = sb + (uint32_t)((kb & (NSTG - 1)) * STAGE);
        #pragma unroll
        for (int ks = 0; ks < 2; ks++) {
            const uint32_t kB = (uint32_t)(ks * 32);
            uint32_t afh[4][4], afl[4][4], bf[4][2];
            #pragma unroll
            for (int mt = 0; mt < 4; mt++) {
                uint32_t ao = st + (a_row + mt * 16) * ROWB + kB + a_colb;
                LDMATRIX_X4(afh[mt][0], afh[mt][1], afh[mt][2], afh[mt][3], ao);
                LDMATRIX_X4(afl[mt][0], afl[mt][1], afl[mt][2], afl[mt][3], ao + ARR_BYTES);
            }
            #pragma unroll
            for (int nt = 0; nt < 4; nt++) {
                uint32_t bo = st + 2 * ARR_BYTES + (b_row + nt * 8) * ROWB + kB + b_colb;
                LDMATRIX_X2(bf[nt][0], bf[nt][1], bo);
            }
            #pragma unroll
            for (int mt = 0; mt < 4; mt++)
                #pragma unroll
                for (int nt = 0; nt < 4; nt++) {
                    MMA_F16(acc[mt][nt], afh[mt], bf[nt]);
                    MMA_F16(acc[mt][nt], afl[mt], bf[nt]);
                }
        }
    }
}

// ---------------- GEMM1: qkv with fused bias+rope+softmax+scatter ----------
#define EPS 132   // epi row stride (floats)

__global__ __launch_bounds__(256, 1)
void mma_gemm_qkv(const __half* __restrict__ Ahi, const __half* __restrict__ Alo,
                  const __half* __restrict__ Bw,
                  const float* __restrict__ rope,
                  const float* __restrict__ q_bias, const float* __restrict__ v_bias,
                  float* __restrict__ phiq, float* __restrict__ phik, float* __restrict__ vout)
{
    extern __shared__ char smem[];
    const uint32_t sb = smem_to_u32(smem);
    const int tid = threadIdx.x, wid = tid >> 5, lane = tid & 31;
    const int bm = blockIdx.y * BM, bn = blockIdx.x * BN;

    float acc[4][4][4];
    gemm_mainloop(Ahi, Alo, Bw, bm, bn, sb, tid, wid, lane, acc);
    __syncthreads();

    // dump accumulators to smem
    float* epi = (float*)smem;
    const int wm = (wid & 1) * 64, wn = (wid >> 1) * 32;
    const int er = lane >> 2, ec = (lane & 3) * 2;
    #pragma unroll
    for (int mt = 0; mt < 4; mt++)
        #pragma unroll
        for (int nt = 0; nt < 4; nt++) {
            int r0 = wm + mt * 16 + er, c = wn + nt * 8 + ec;
            *(float2*)&epi[r0 * EPS + c]       = make_float2(acc[mt][nt][0], acc[mt][nt][1]);
            *(float2*)&epi[(r0 + 8) * EPS + c] = make_float2(acc[mt][nt][2], acc[mt][nt][3]);
        }
    __syncthreads();

    // fused epilogue (tiles never straddle q/k/v: 768 % 128 == 0)
    const int region = bn / C_;            // 0=q, 1=k, 2=v
    const int col0   = bn - region * C_;
    const float* bias = (region == 0) ? q_bias : (region == 2 ? v_bias : nullptr);
    float* outbuf = (region == 0) ? phiq : (region == 1 ? phik : vout);

    const int sub    = lane >> 4;
    const int lane15 = lane & 15;
    const int g      = lane15 >> 3;        // head within tile (0/1)
    const int dof    = (lane15 & 7) << 3;  // d offset (0..56)
    const int h      = (col0 >> 6) + g;

    #pragma unroll 2
    for (int rr = 0; rr < 8; rr++) {
        const int row  = wid * 16 + rr * 2 + sub;
        const int gtok = bm + row;
        const int b    = gtok >> 12;
        const int n    = gtok & (NTOK - 1);

        float4 v0 = *(float4*)&epi[row * EPS + g * 64 + dof];
        float4 v1 = *(float4*)&epi[row * EPS + g * 64 + dof + 4];
        float vals[8] = { v0.x, v0.y, v0.z, v0.w, v1.x, v1.y, v1.z, v1.w };

        if (bias) {
            #pragma unroll
            for (int j = 0; j < 8; j++) vals[j] += bias[col0 + g * 64 + dof + j];
        }

        if (region != 2) {
            if (n >= 1) {
                const float* rp = rope + (size_t)(n - 1) * (2 * D_) + dof;
                float4 s0 = *(const float4*)rp;
                float4 s1 = *(const float4*)(rp + 4);
                float4 c0 = *(const float4*)(rp + 64);
                float4 c1 = *(const float4*)(rp + 68);
                float snv[8] = { s0.x, s0.y, s0.z, s0.w, s1.x, s1.y, s1.z, s1.w };
                float csv[8] = { c0.x, c0.y, c0.z, c0.w, c1.x, c1.y, c1.z, c1.w };
                #pragma unroll
                for (int p = 0; p < 4; p++) {
                    float t0 = vals[2 * p], t1 = vals[2 * p + 1];
                    vals[2 * p]     = t0 * csv[2 * p]     - t1 * snv[2 * p];
                    vals[2 * p + 1] = t1 * csv[2 * p + 1] + t0 * snv[2 * p + 1];
                }
            }
            // softmax over the 8-lane head group
            float m = vals[0];
            #pragma unroll
            for (int j = 1; j < 8; j++) m = fmaxf(m, vals[j]);
            #pragma unroll
            for (int o = 1; o < 8; o <<= 1)
                m = fmaxf(m, __shfl_xor_sync(0xffffffffu, m, o));
            float s = 0.f;
            #pragma unroll
            for (int j = 0; j < 8; j++) { vals[j] = expf(vals[j] - m); s += vals[j]; }
            #pragma unroll
            for (int o = 1; o < 8; o <<= 1)
                s += __shfl_xor_sync(0xffffffffu, s, o);
            float rs = 1.f / s;
            #pragma unroll
            for (int j = 0; j < 8; j++) vals[j] *= rs;
        }

        float* dst = outbuf + (((size_t)b * H_ + h) * NTOK + n) * D_ + dof;
        *(float4*)dst       = make_float4(vals[0], vals[1], vals[2], vals[3]);
        *(float4*)(dst + 4) = make_float4(vals[4], vals[5], vals[6], vals[7]);
    }
}

// ---------------- GEMM2: proj with bias ----------------
__global__ __launch_bounds__(256, 1)
void mma_gemm_proj(const __half* __restrict__ Ahi, const __half* __restrict__ Alo,
                   const __half* __restrict__ Bw,
                   float* __restrict__ Cc, int N, const float* __restrict__ bias_full)
{
    extern __shared__ char smem[];
    const uint32_t sb = smem_to_u32(smem);
    const int tid = threadIdx.x, wid = tid >> 5, lane = tid & 31;
    const int bm = blockIdx.y * BM, bn = blockIdx.x * BN;

    float acc[4][4][4];
    gemm_mainloop(Ahi, Alo, Bw, bm, bn, sb, tid, wid, lane, acc);

    const int wm = (wid & 1) * 64, wn = (wid >> 1) * 32;
    const int er = lane >> 2, ec = (lane & 3) * 2;
    #pragma unroll
    for (int mt = 0; mt < 4; mt++) {
        #pragma unroll
        for (int nt = 0; nt < 4; nt++) {
            int row = bm + wm + mt * 16 + er;
            int col = bn + wn + nt * 8 + ec;
            float b0 = bias_full[col], b1 = bias_full[col + 1];
            *(float2*)(Cc + (size_t)row * N + col) =
                make_float2(acc[mt][nt][0] + b0, acc[mt][nt][1] + b1);
            *(float2*)(Cc + (size_t)(row + 8) * N + col) =
                make_float2(acc[mt][nt][2] + b0, acc[mt][nt][3] + b1);
        }
    }
}

// ---------------- fp32 -> fp16 hi/lo split ----------------
__global__ void cvt_split_h(const float* __restrict__ x,
                            __half* __restrict__ hi,
                            __half* __restrict__ lo, int n4)
{
    int i = blockIdx.x * blockDim.x + threadIdx.x;
    if (i >= n4) return;
    float4 f = ((const float4*)x)[i];
    __half h[4], l[4];
    #pragma unroll
    for (int j = 0; j < 4; j++) {
        float fv = ((const float*)&f)[j];
        h[j] = __float2half(fv);
        l[j] = __float2half(fv - __half2float(h[j]));
    }
    ((uint2*)hi)[i] = *(uint2*)h;
    ((uint2*)lo)[i] = *(uint2*)l;
}

// ---------------- fp32 -> fp16 (weights, single) ----------------
__global__ void cvt_h(const float* __restrict__ x, __half* __restrict__ y, int n4)
{
    int i = blockIdx.x * blockDim.x + threadIdx.x;
    if (i >= n4) return;
    float4 f = ((const float4*)x)[i];
    __half h[4];
    h[0] = __float2half(f.x); h[1] = __float2half(f.y);
    h[2] = __float2half(f.z); h[3] = __float2half(f.w);
    ((uint2*)y)[i] = *(uint2*)h;
}

// ---------------- zero helper ------------------------------------------------
__global__ void zero_kernel(float* __restrict__ p, int n)
{
    int i = blockIdx.x * blockDim.x + threadIdx.x;
    if (i < n) p[i] = 0.f;
}

// ---------------- kv + ksum reduction ----------------------------------------
#define KV_SPLIT 8
__global__ void kv_kernel(const float* __restrict__ phik,
                          const float* __restrict__ v,
                          float* __restrict__ kv,
                          float* __restrict__ ksum)
{
    int bh  = blockIdx.x;
    int seg = blockIdx.y;
    int tid = threadIdx.x;

    const float* pk = phik + (size_t)bh * NTOK * D_;
    const float* pv = v    + (size_t)bh * NTOK * D_;
    int n0 = seg * (NTOK / KV_SPLIT);

    __shared__ float sk[16][64];
    __shared__ float sv[16][64];

    int td = (tid >> 4) << 2;
    int te = (tid & 15) << 2;
    int r  = tid >> 4;
    int c4 = (tid & 15) << 2;

    float acc[4][4];
#pragma unroll
    for (int i = 0; i < 4; i++)
#pragma unroll
        for (int j = 0; j < 4; j++) acc[i][j] = 0.f;
    float ksl = 0.f;

    for (int nc = n0; nc < n0 + NTOK / KV_SPLIT; nc += 16) {
        *(float4*)&sk[r][c4] = *(const float4*)(pk + (size_t)(nc + r) * D_ + c4);
        *(float4*)&sv[r][c4] = *(const float4*)(pv + (size_t)(nc + r) * D_ + c4);
        __syncthreads();
#pragma unroll
        for (int nn = 0; nn < 16; nn++) {
            float a[4], b[4];
            *(float4*)a = *(const float4*)&sk[nn][td];
            *(float4*)b = *(const float4*)&sv[nn][te];
#pragma unroll
            for (int i = 0; i < 4; i++)
#pragma unroll
                for (int j = 0; j < 4; j++)
                    acc[i][j] = fmaf(a[i], b[j], acc[i][j]);
        }
        if (tid < D_) {
#pragma unroll
            for (int nn = 0; nn < 16; nn++) ksl += sk[nn][tid];
        }
        __syncthreads();
    }

    float* kvb = kv + (size_t)bh * D_ * D_;
#pragma unroll
    for (int i = 0; i < 4; i++)
#pragma unroll
        for (int j = 0; j < 4; j++)
            atomicAdd(&kvb[(td + i) * D_ + te + j], acc[i][j]);
    if (tid < D_) atomicAdd(&ksum[bh * D_ + tid], ksl);
}

// ---------------- attention output -------------------------------------------
__global__ void attn_out_kernel(const float* __restrict__ phiq,
                                const float* __restrict__ kv,
                                const float* __restrict__ ksum,
                                float* __restrict__ outp)
{
    int bh   = blockIdx.x;
    int tgrp = blockIdx.y;
    int tid  = threadIdx.x;

    __shared__ float skv[D_][D_];
    __shared__ float sks[D_];
    __shared__ float spq[8][D_];

    const float* kvb = kv + (size_t)bh * D_ * D_;
    for (int i = tid; i < D_ * D_ / 4; i += 256)
        ((float4*)skv)[i] = ((const float4*)kvb)[i];
    if (tid < D_) sks[tid] = ksum[bh * D_ + tid];
    __syncthreads();

    int warp = tid >> 5, lane = tid & 31;
    int n = tgrp * 8 + warp;

    const float* pq = phiq + ((size_t)bh * NTOK + n) * D_;
    float2 qp = ((const float2*)pq)[lane];
    spq[warp][2 * lane]     = qp.x;
    spq[warp][2 * lane + 1] = qp.y;
    __syncwarp();

    float z = qp.x * sks[2 * lane] + qp.y * sks[2 * lane + 1];
#pragma unroll
    for (int o = 16; o > 0; o >>= 1) z += __shfl_xor_sync(0xffffffffu, z, o);
    float rz = 1.f / (z + 1e-5f);

    float o0 = 0.f, o1 = 0.f;
#pragma unroll 16
    for (int d = 0; d < D_; d++) {
        float p = spq[warp][d];
        float2 kvp = ((const float2*)&skv[d][0])[lane];
        o0 = fmaf(p, kvp.x, o0);
        o1 = fmaf(p, kvp.y, o1);
    }

    int b = bh / H_, h = bh % H_;
    float* orow = outp + ((size_t)(b * NTOK + n)) * C_ + h * D_;
    ((float2*)orow)[lane] = make_float2(o0 * rz, o1 * rz);
}

// ---------------- layernorm -> split fp16 ------------------------------------
__global__ void ln_kernel(const float* __restrict__ x,
                          const float* __restrict__ g,
                          const float* __restrict__ b,
                          __half* __restrict__ yhi,
                          __half* __restrict__ ylo)
{
    int row = blockIdx.x;
    int tid = threadIdx.x; // 256
    const float* xr = x + (size_t)row * C_;

    float v0 = xr[tid], v1 = xr[tid + 256], v2 = xr[tid + 512];
    float s  = v0 + v1 + v2;
    float ss = v0 * v0 + v1 * v1 + v2 * v2;
#pragma unroll
    for (int o = 16; o > 0; o >>= 1) {
        s  += __shfl_xor_sync(0xffffffffu, s,  o);
        ss += __shfl_xor_sync(0xffffffffu, ss, o);
    }
    __shared__ float ws[8], wss[8];
    int warp = tid >> 5, lane = tid & 31;
    if (lane == 0) { ws[warp] = s; wss[warp] = ss; }
    __syncthreads();
    if (tid == 0) {
        float ts = 0.f, tss = 0.f;
#pragma unroll
        for (int i = 0; i < 8; i++) { ts += ws[i]; tss += wss[i]; }
        ws[0] = ts; wss[0] = tss;
    }
    __syncthreads();
    float mean = ws[0] * (1.f / C_);
    float var  = wss[0] * (1.f / C_) - mean * mean;
    float inv  = rsqrtf(var + 1e-5f);

    size_t rb = (size_t)row * C_;
#pragma unroll
    for (int j = 0; j < 3; j++) {
        int c = tid + j * 256;
        float vv = (j == 0 ? v0 : (j == 1 ? v1 : v2));
        float y = (vv - mean) * inv * g[c] + b[c];
        __half hh = __float2half(y);
        yhi[rb + c] = hh;
        ylo[rb + c] = __float2half(y - __half2float(hh));
    }
}

// ---------------- launch ------------------------------------------------------
extern "C" void kernel_launch(void* const* d_in, const int* in_sizes, int n_in,
                              void* d_out, int out_size)
{
    (void)in_sizes; (void)n_in; (void)out_size;
    const float* x      = (const float*)d_in[0];
    const float* rope   = (const float*)d_in[1];
    const float* qkv_w  = (const float*)d_in[2];
    const float* q_bias = (const float*)d_in[3];
    const float* v_bias = (const float*)d_in[4];
    const float* norm_g = (const float*)d_in[5];
    const float* norm_b = (const float*)d_in[6];
    const float* proj_w = (const float*)d_in[7];
    const float* proj_b = (const float*)d_in[8];
    float* out = (float*)d_out;

    float *phiq, *phik, *v, *kv, *ksum, *attn;
    __half *xhi, *xlo, *w, *pw, *lhi, *llo;
    cudaGetSymbolAddress((void**)&phiq, g_phiq);
    cudaGetSymbolAddress((void**)&phik, g_phik);
    cudaGetSymbolAddress((void**)&v,    g_v);
    cudaGetSymbolAddress((void**)&kv,   g_kv);
    cudaGetSymbolAddress((void**)&ksum, g_ksum);
    cudaGetSymbolAddress((void**)&attn, g_attn);
    cudaGetSymbolAddress((void**)&xhi,  g_xhi);
    cudaGetSymbolAddress((void**)&xlo,  g_xlo);
    cudaGetSymbolAddress((void**)&w,    g_w);
    cudaGetSymbolAddress((void**)&pw,   g_pw);
    cudaGetSymbolAddress((void**)&lhi,  g_lhi);
    cudaGetSymbolAddress((void**)&llo,  g_llo);

    cudaFuncSetAttribute(mma_gemm_qkv,  cudaFuncAttributeMaxDynamicSharedMemorySize, SMEM_GEMM);
    cudaFuncSetAttribute(mma_gemm_proj, cudaFuncAttributeMaxDynamicSharedMemorySize, SMEM_GEMM);

    // 0) conversions
    {
        int n4 = (M_ * KDIM) / 4;
        cvt_split_h<<<(n4 + 255) / 256, 256>>>(x, xhi, xlo, n4);
        n4 = (QKVN * KDIM) / 4;
        cvt_h<<<(n4 + 255) / 256, 256>>>(qkv_w, w, n4);
        n4 = (C_ * KDIM) / 4;
        cvt_h<<<(n4 + 255) / 256, 256>>>(proj_w, pw, n4);
    }

    // 1) fused qkv GEMM + bias + rope + softmax + head-scatter
    mma_gemm_qkv<<<dim3(QKVN / BN, M_ / BM), 256, SMEM_GEMM>>>(
        xhi, xlo, w, rope, q_bias, v_bias, phiq, phik, v);

    // 2) zero accumulators
    zero_kernel<<<(B_ * H_ * D_ * D_ + 1023) / 1024, 1024>>>(kv, B_ * H_ * D_ * D_);
    zero_kernel<<<(B_ * H_ * D_ + 1023) / 1024, 1024>>>(ksum, B_ * H_ * D_);

    // 3) kv & ksum reductions
    kv_kernel<<<dim3(B_ * H_, KV_SPLIT), 256>>>(phik, v, kv, ksum);

    // 4) attention output
    attn_out_kernel<<<dim3(B_ * H_, NTOK / 8), 256>>>(phiq, kv, ksum, attn);

    // 5) layernorm (fused split-fp16 output)
    ln_kernel<<<M_, 256>>>(attn, norm_g, norm_b, lhi, llo);

    // 6) out = ln @ proj_w^T + proj_b
    mma_gemm_proj<<<dim3(C_ / BN, M_ / BM), 256, SMEM_GEMM>>>(
        lhi, llo, pw, out, C_, proj_b);
}

// round 7
// speedup vs baseline: 1.9305x; 1.5008x over previous
#include <cuda_runtime.h>
#include <cuda_fp16.h>
#include <cstdint>

// ---------------- problem constants ----------------
#define B_    8
#define NTOK  4096
#define C_    768
#define H_    12
#define D_    64
#define M_    (B_ * NTOK)     // 32768
#define QKVN  (3 * C_)        // 2304
#define KDIM  768

// ---------------- scratch (device globals) ----------------
__device__ float g_phiq[(size_t)B_ * H_ * NTOK * D_];
__device__ float g_phik[(size_t)B_ * H_ * NTOK * D_];
__device__ float g_v   [(size_t)B_ * H_ * NTOK * D_];
__device__ float g_kv  [B_ * H_ * D_ * D_];
__device__ float g_ksum[B_ * H_ * D_];
__device__ float g_attn[(size_t)M_ * C_];

__device__ __half g_xh [(size_t)M_ * KDIM];
__device__ __half g_w  [(size_t)QKVN * KDIM];
__device__ __half g_pw [(size_t)C_ * KDIM];
__device__ __half g_lh [(size_t)M_ * KDIM];

// ---------------- low-level helpers ----------------
__device__ __forceinline__ uint32_t smem_to_u32(const void* p) {
    uint32_t a;
    asm("{ .reg .u64 t; cvta.to.shared.u64 t, %1; cvt.u32.u64 %0, t; }"
        : "=r"(a) : "l"(p));
    return a;
}

#define CP_ASYNC_CG(dst, src) \
    asm volatile("cp.async.cg.shared.global [%0], [%1], 16;" :: "r"(dst), "l"(src))
#define CP_COMMIT()  asm volatile("cp.async.commit_group;" ::: "memory")
#define CP_WAIT(N)   asm volatile("cp.async.wait_group %0;" :: "n"(N) : "memory")

#define LDMATRIX_X4(r0, r1, r2, r3, addr) \
    asm volatile("ldmatrix.sync.aligned.m8n8.x4.shared.b16 {%0,%1,%2,%3}, [%4];" \
        : "=r"(r0), "=r"(r1), "=r"(r2), "=r"(r3) : "r"(addr))
#define LDMATRIX_X2(r0, r1, addr) \
    asm volatile("ldmatrix.sync.aligned.m8n8.x2.shared.b16 {%0,%1}, [%2];" \
        : "=r"(r0), "=r"(r1) : "r"(addr))

#define MMA_F16(d, a, b) \
    asm volatile("mma.sync.aligned.m16n8k16.row.col.f32.f16.f16.f32 " \
        "{%0,%1,%2,%3}, {%4,%5,%6,%7}, {%8,%9}, {%0,%1,%2,%3};" \
        : "+f"((d)[0]), "+f"((d)[1]), "+f"((d)[2]), "+f"((d)[3]) \
        : "r"((a)[0]), "r"((a)[1]), "r"((a)[2]), "r"((a)[3]), \
          "r"((b)[0]), "r"((b)[1]))

// ---------------- GEMM tiling (single-term fp16) ----------------
#define BM 128
#define BN 128
#define BKB 32                   // f16 k-elems per stage
#define KB  (KDIM / BKB)         // 24 k-blocks
#define ROWB 80                  // padded row stride in bytes
#define ARR_BYTES (128 * ROWB)   // 10240 per operand array
#define STAGE (2 * ARR_BYTES)    // A, B = 20480
#define NSTG 4
#define SMEM_GEMM (NSTG * STAGE) // 81920

// 4-stage cp.async mainloop; warp tile 64x32; acc[4][4][4] fp32; 1 MMA/tile.
__device__ __forceinline__ void gemm_mainloop(
    const __half* __restrict__ A, const __half* __restrict__ Bw,
    int bm, int bn, uint32_t sb, int tid, int wid, int lane,
    float acc[4][4][4])
{
    const int wm = (wid & 1) * 64;
    const int wn = (wid >> 1) * 32;

    // per-thread cp.async source/dest: 4 x 16B chunks per stage
    const int lrow = tid >> 2;           // 0..63
    const int lch  = tid & 3;            // chunk-in-row
    const __half* srcs[4];
    uint32_t dsts[4];
    {
        const __half* bases[2] = { A, Bw };
        #pragma unroll
        for (int i = 0; i < 4; i++) {
            int arr = i >> 1;
            int row = (i & 1) * 64 + lrow;
            int roff = (arr == 0) ? (bm + row) : (bn + row);
            srcs[i] = bases[arr] + (size_t)roff * KDIM + lch * 8;
            dsts[i] = sb + arr * ARR_BYTES + row * ROWB + lch * 16;
        }
    }

    const uint32_t a_row  = (uint32_t)(wm + (lane & 7) + ((lane >> 3) & 1) * 8);
    const uint32_t a_colb = (uint32_t)(((lane >> 4) & 1) * 16);
    const uint32_t b_row  = (uint32_t)(wn + (lane & 7));
    const uint32_t b_colb = (uint32_t)(((lane >> 3) & 1) * 16);

    #pragma unroll
    for (int i = 0; i < 4; i++)
        #pragma unroll
        for (int j = 0; j < 4; j++)
            #pragma unroll
            for (int r = 0; r < 4; r++) acc[i][j][r] = 0.f;

    // preload stages 0,1
    #pragma unroll
    for (int p = 0; p < 2; p++) {
        const uint32_t so = (uint32_t)(p * STAGE);
        const int k0 = p * BKB;
        #pragma unroll
        for (int i = 0; i < 4; i++) CP_ASYNC_CG(dsts[i] + so, srcs[i] + k0);
        CP_COMMIT();
    }

    for (int kb = 0; kb < KB; kb++) {
        const int pf = kb + 2;
        if (pf < KB) {
            const uint32_t so = (uint32_t)((pf & (NSTG - 1)) * STAGE);
            const int k0 = pf * BKB;
            #pragma unroll
            for (int i = 0; i < 4; i++) CP_ASYNC_CG(dsts[i] + so, srcs[i] + k0);
        }
        CP_COMMIT();
        CP_WAIT(2);
        __syncthreads();

        const uint32_t st = sb + (uint32_t)((kb & (NSTG - 1)) * STAGE);
        #pragma unroll
        for (int ks = 0; ks < 2; ks++) {
            const uint32_t kB = (uint32_t)(ks * 32);
            uint32_t af[4][4], bf[4][2];
            #pragma unroll
            for (int mt = 0; mt < 4; mt++) {
                uint32_t ao = st + (a_row + mt * 16) * ROWB + kB + a_colb;
                LDMATRIX_X4(af[mt][0], af[mt][1], af[mt][2], af[mt][3], ao);
            }
            #pragma unroll
            for (int nt = 0; nt < 4; nt++) {
                uint32_t bo = st + ARR_BYTES + (b_row + nt * 8) * ROWB + kB + b_colb;
                LDMATRIX_X2(bf[nt][0], bf[nt][1], bo);
            }
            #pragma unroll
            for (int mt = 0; mt < 4; mt++)
                #pragma unroll
                for (int nt = 0; nt < 4; nt++)
                    MMA_F16(acc[mt][nt], af[mt], bf[nt]);
        }
    }
}

// ---------------- GEMM1: qkv with fused bias+rope+softmax+scatter ----------
#define EPS 132   // epi row stride (floats)

__global__ __launch_bounds__(256, 2)
void mma_gemm_qkv(const __half* __restrict__ A, const __half* __restrict__ Bw,
                  const float* __restrict__ rope,
                  const float* __restrict__ q_bias, const float* __restrict__ v_bias,
                  float* __restrict__ phiq, float* __restrict__ phik, float* __restrict__ vout)
{
    extern __shared__ char smem[];
    const uint32_t sb = smem_to_u32(smem);
    const int tid = threadIdx.x, wid = tid >> 5, lane = tid & 31;
    const int bm = blockIdx.y * BM, bn = blockIdx.x * BN;

    float acc[4][4][4];
    gemm_mainloop(A, Bw, bm, bn, sb, tid, wid, lane, acc);
    __syncthreads();

    // dump accumulators to smem (128x128, stride 132) — fits in 67584 B < 81920
    float* epi = (float*)smem;
    const int wm = (wid & 1) * 64, wn = (wid >> 1) * 32;
    const int er = lane >> 2, ec = (lane & 3) * 2;
    #pragma unroll
    for (int mt = 0; mt < 4; mt++)
        #pragma unroll
        for (int nt = 0; nt < 4; nt++) {
            int r0 = wm + mt * 16 + er, c = wn + nt * 8 + ec;
            *(float2*)&epi[r0 * EPS + c]       = make_float2(acc[mt][nt][0], acc[mt][nt][1]);
            *(float2*)&epi[(r0 + 8) * EPS + c] = make_float2(acc[mt][nt][2], acc[mt][nt][3]);
        }
    __syncthreads();

    // fused epilogue (tiles never straddle q/k/v: 768 % 128 == 0)
    const int region = bn / C_;            // 0=q, 1=k, 2=v
    const int col0   = bn - region * C_;
    const float* bias = (region == 0) ? q_bias : (region == 2 ? v_bias : nullptr);
    float* outbuf = (region == 0) ? phiq : (region == 1 ? phik : vout);

    const int sub    = lane >> 4;
    const int lane15 = lane & 15;
    const int g      = lane15 >> 3;        // head within tile (0/1)
    const int dof    = (lane15 & 7) << 3;  // d offset (0..56)
    const int h      = (col0 >> 6) + g;

    #pragma unroll 2
    for (int rr = 0; rr < 8; rr++) {
        const int row  = wid * 16 + rr * 2 + sub;
        const int gtok = bm + row;
        const int b    = gtok >> 12;
        const int n    = gtok & (NTOK - 1);

        float4 v0 = *(float4*)&epi[row * EPS + g * 64 + dof];
        float4 v1 = *(float4*)&epi[row * EPS + g * 64 + dof + 4];
        float vals[8] = { v0.x, v0.y, v0.z, v0.w, v1.x, v1.y, v1.z, v1.w };

        if (bias) {
            #pragma unroll
            for (int j = 0; j < 8; j++) vals[j] += bias[col0 + g * 64 + dof + j];
        }

        if (region != 2) {
            if (n >= 1) {
                const float* rp = rope + (size_t)(n - 1) * (2 * D_) + dof;
                float4 s0 = *(const float4*)rp;
                float4 s1 = *(const float4*)(rp + 4);
                float4 c0 = *(const float4*)(rp + 64);
                float4 c1 = *(const float4*)(rp + 68);
                float snv[8] = { s0.x, s0.y, s0.z, s0.w, s1.x, s1.y, s1.z, s1.w };
                float csv[8] = { c0.x, c0.y, c0.z, c0.w, c1.x, c1.y, c1.z, c1.w };
                #pragma unroll
                for (int p = 0; p < 4; p++) {
                    float t0 = vals[2 * p], t1 = vals[2 * p + 1];
                    vals[2 * p]     = t0 * csv[2 * p]     - t1 * snv[2 * p];
                    vals[2 * p + 1] = t1 * csv[2 * p + 1] + t0 * snv[2 * p + 1];
                }
            }
            // softmax over the 8-lane head group
            float m = vals[0];
            #pragma unroll
            for (int j = 1; j < 8; j++) m = fmaxf(m, vals[j]);
            #pragma unroll
            for (int o = 1; o < 8; o <<= 1)
                m = fmaxf(m, __shfl_xor_sync(0xffffffffu, m, o));
            float s = 0.f;
            #pragma unroll
            for (int j = 0; j < 8; j++) { vals[j] = expf(vals[j] - m); s += vals[j]; }
            #pragma unroll
            for (int o = 1; o < 8; o <<= 1)
                s += __shfl_xor_sync(0xffffffffu, s, o);
            float rs = 1.f / s;
            #pragma unroll
            for (int j = 0; j < 8; j++) vals[j] *= rs;
        }

        float* dst = outbuf + (((size_t)b * H_ + h) * NTOK + n) * D_ + dof;
        *(float4*)dst       = make_float4(vals[0], vals[1], vals[2], vals[3]);
        *(float4*)(dst + 4) = make_float4(vals[4], vals[5], vals[6], vals[7]);
    }
}

// ---------------- GEMM2: proj with bias ----------------
__global__ __launch_bounds__(256, 2)
void mma_gemm_proj(const __half* __restrict__ A, const __half* __restrict__ Bw,
                   float* __restrict__ Cc, int N, const float* __restrict__ bias_full)
{
    extern __shared__ char smem[];
    const uint32_t sb = smem_to_u32(smem);
    const int tid = threadIdx.x, wid = tid >> 5, lane = tid & 31;
    const int bm = blockIdx.y * BM, bn = blockIdx.x * BN;

    float acc[4][4][4];
    gemm_mainloop(A, Bw, bm, bn, sb, tid, wid, lane, acc);

    const int wm = (wid & 1) * 64, wn = (wid >> 1) * 32;
    const int er = lane >> 2, ec = (lane & 3) * 2;
    #pragma unroll
    for (int mt = 0; mt < 4; mt++) {
        #pragma unroll
        for (int nt = 0; nt < 4; nt++) {
            int row = bm + wm + mt * 16 + er;
            int col = bn + wn + nt * 8 + ec;
            float b0 = bias_full[col], b1 = bias_full[col + 1];
            *(float2*)(Cc + (size_t)row * N + col) =
                make_float2(acc[mt][nt][0] + b0, acc[mt][nt][1] + b1);
            *(float2*)(Cc + (size_t)(row + 8) * N + col) =
                make_float2(acc[mt][nt][2] + b0, acc[mt][nt][3] + b1);
        }
    }
}

// ---------------- fp32 -> fp16 ----------------
__global__ void cvt_h(const float* __restrict__ x, __half* __restrict__ y, int n4)
{
    int i = blockIdx.x * blockDim.x + threadIdx.x;
    if (i >= n4) return;
    float4 f = ((const float4*)x)[i];
    __half h[4];
    h[0] = __float2half(f.x); h[1] = __float2half(f.y);
    h[2] = __float2half(f.z); h[3] = __float2half(f.w);
    ((uint2*)y)[i] = *(uint2*)h;
}

// ---------------- zero helper ------------------------------------------------
__global__ void zero_kernel(float* __restrict__ p, int n)
{
    int i = blockIdx.x * blockDim.x + threadIdx.x;
    if (i < n) p[i] = 0.f;
}

// ---------------- kv + ksum reduction ----------------------------------------
#define KV_SPLIT 8
__global__ void kv_kernel(const float* __restrict__ phik,
                          const float* __restrict__ v,
                          float* __restrict__ kv,
                          float* __restrict__ ksum)
{
    int bh  = blockIdx.x;
    int seg = blockIdx.y;
    int tid = threadIdx.x;

    const float* pk = phik + (size_t)bh * NTOK * D_;
    const float* pv = v    + (size_t)bh * NTOK * D_;
    int n0 = seg * (NTOK / KV_SPLIT);

    __shared__ float sk[16][64];
    __shared__ float sv[16][64];

    int td = (tid >> 4) << 2;
    int te = (tid & 15) << 2;
    int r  = tid >> 4;
    int c4 = (tid & 15) << 2;

    float acc[4][4];
#pragma unroll
    for (int i = 0; i < 4; i++)
#pragma unroll
        for (int j = 0; j < 4; j++) acc[i][j] = 0.f;
    float ksl = 0.f;

    for (int nc = n0; nc < n0 + NTOK / KV_SPLIT; nc += 16) {
        *(float4*)&sk[r][c4] = *(const float4*)(pk + (size_t)(nc + r) * D_ + c4);
        *(float4*)&sv[r][c4] = *(const float4*)(pv + (size_t)(nc + r) * D_ + c4);
        __syncthreads();
#pragma unroll
        for (int nn = 0; nn < 16; nn++) {
            float a[4], b[4];
            *(float4*)a = *(const float4*)&sk[nn][td];
            *(float4*)b = *(const float4*)&sv[nn][te];
#pragma unroll
            for (int i = 0; i < 4; i++)
#pragma unroll
                for (int j = 0; j < 4; j++)
                    acc[i][j] = fmaf(a[i], b[j], acc[i][j]);
        }
        if (tid < D_) {
#pragma unroll
            for (int nn = 0; nn < 16; nn++) ksl += sk[nn][tid];
        }
        __syncthreads();
    }

    float* kvb = kv + (size_t)bh * D_ * D_;
#pragma unroll
    for (int i = 0; i < 4; i++)
#pragma unroll
        for (int j = 0; j < 4; j++)
            atomicAdd(&kvb[(td + i) * D_ + te + j], acc[i][j]);
    if (tid < D_) atomicAdd(&ksum[bh * D_ + tid], ksl);
}

// ---------------- attention output -------------------------------------------
__global__ void attn_out_kernel(const float* __restrict__ phiq,
                                const float* __restrict__ kv,
                                const float* __restrict__ ksum,
                                float* __restrict__ outp)
{
    int bh   = blockIdx.x;
    int tgrp = blockIdx.y;
    int tid  = threadIdx.x;

    __shared__ float skv[D_][D_];
    __shared__ float sks[D_];
    __shared__ float spq[8][D_];

    const float* kvb = kv + (size_t)bh * D_ * D_;
    for (int i = tid; i < D_ * D_ / 4; i += 256)
        ((float4*)skv)[i] = ((const float4*)kvb)[i];
    if (tid < D_) sks[tid] = ksum[bh * D_ + tid];
    __syncthreads();

    int warp = tid >> 5, lane = tid & 31;
    int n = tgrp * 8 + warp;

    const float* pq = phiq + ((size_t)bh * NTOK + n) * D_;
    float2 qp = ((const float2*)pq)[lane];
    spq[warp][2 * lane]     = qp.x;
    spq[warp][2 * lane + 1] = qp.y;
    __syncwarp();

    float z = qp.x * sks[2 * lane] + qp.y * sks[2 * lane + 1];
#pragma unroll
    for (int o = 16; o > 0; o >>= 1) z += __shfl_xor_sync(0xffffffffu, z, o);
    float rz = 1.f / (z + 1e-5f);

    float o0 = 0.f, o1 = 0.f;
#pragma unroll 16
    for (int d = 0; d < D_; d++) {
        float p = spq[warp][d];
        float2 kvp = ((const float2*)&skv[d][0])[lane];
        o0 = fmaf(p, kvp.x, o0);
        o1 = fmaf(p, kvp.y, o1);
    }

    int b = bh / H_, h = bh % H_;
    float* orow = outp + ((size_t)(b * NTOK + n)) * C_ + h * D_;
    ((float2*)orow)[lane] = make_float2(o0 * rz, o1 * rz);
}

// ---------------- layernorm -> fp16 ------------------------------------------
__global__ void ln_kernel(const float* __restrict__ x,
                          const float* __restrict__ g,
                          const float* __restrict__ b,
                          __half* __restrict__ yh)
{
    int row = blockIdx.x;
    int tid = threadIdx.x; // 256
    const float* xr = x + (size_t)row * C_;

    float v0 = xr[tid], v1 = xr[tid + 256], v2 = xr[tid + 512];
    float s  = v0 + v1 + v2;
    float ss = v0 * v0 + v1 * v1 + v2 * v2;
#pragma unroll
    for (int o = 16; o > 0; o >>= 1) {
        s  += __shfl_xor_sync(0xffffffffu, s,  o);
        ss += __shfl_xor_sync(0xffffffffu, ss, o);
    }
    __shared__ float ws[8], wss[8];
    int warp = tid >> 5, lane = tid & 31;
    if (lane == 0) { ws[warp] = s; wss[warp] = ss; }
    __syncthreads();
    if (tid == 0) {
        float ts = 0.f, tss = 0.f;
#pragma unroll
        for (int i = 0; i < 8; i++) { ts += ws[i]; tss += wss[i]; }
        ws[0] = ts; wss[0] = tss;
    }
    __syncthreads();
    float mean = ws[0] * (1.f / C_);
    float var  = wss[0] * (1.f / C_) - mean * mean;
    float inv  = rsqrtf(var + 1e-5f);

    size_t rb = (size_t)row * C_;
#pragma unroll
    for (int j = 0; j < 3; j++) {
        int c = tid + j * 256;
        float vv = (j == 0 ? v0 : (j == 1 ? v1 : v2));
        float y = (vv - mean) * inv * g[c] + b[c];
        yh[rb + c] = __float2half(y);
    }
}

// ---------------- launch ------------------------------------------------------
extern "C" void kernel_launch(void* const* d_in, const int* in_sizes, int n_in,
                              void* d_out, int out_size)
{
    (void)in_sizes; (void)n_in; (void)out_size;
    const float* x      = (const float*)d_in[0];
    const float* rope   = (const float*)d_in[1];
    const float* qkv_w  = (const float*)d_in[2];
    const float* q_bias = (const float*)d_in[3];
    const float* v_bias = (const float*)d_in[4];
    const float* norm_g = (const float*)d_in[5];
    const float* norm_b = (const float*)d_in[6];
    const float* proj_w = (const float*)d_in[7];
    const float* proj_b = (const float*)d_in[8];
    float* out = (float*)d_out;

    float *phiq, *phik, *v, *kv, *ksum, *attn;
    __half *xh, *w, *pw, *lh;
    cudaGetSymbolAddress((void**)&phiq, g_phiq);
    cudaGetSymbolAddress((void**)&phik, g_phik);
    cudaGetSymbolAddress((void**)&v,    g_v);
    cudaGetSymbolAddress((void**)&kv,   g_kv);
    cudaGetSymbolAddress((void**)&ksum, g_ksum);
    cudaGetSymbolAddress((void**)&attn, g_attn);
    cudaGetSymbolAddress((void**)&xh,   g_xh);
    cudaGetSymbolAddress((void**)&w,    g_w);
    cudaGetSymbolAddress((void**)&pw,   g_pw);
    cudaGetSymbolAddress((void**)&lh,   g_lh);

    cudaFuncSetAttribute(mma_gemm_qkv,  cudaFuncAttributeMaxDynamicSharedMemorySize, SMEM_GEMM);
    cudaFuncSetAttribute(mma_gemm_proj, cudaFuncAttributeMaxDynamicSharedMemorySize, SMEM_GEMM);

    // 0) conversions
    {
        int n4 = (M_ * KDIM) / 4;
        cvt_h<<<(n4 + 255) / 256, 256>>>(x, xh, n4);
        n4 = (QKVN * KDIM) / 4;
        cvt_h<<<(n4 + 255) / 256, 256>>>(qkv_w, w, n4);
        n4 = (C_ * KDIM) / 4;
        cvt_h<<<(n4 + 255) / 256, 256>>>(proj_w, pw, n4);
    }

    // 1) fused qkv GEMM + bias + rope + softmax + head-scatter
    mma_gemm_qkv<<<dim3(QKVN / BN, M_ / BM), 256, SMEM_GEMM>>>(
        xh, w, rope, q_bias, v_bias, phiq, phik, v);

    // 2) zero accumulators
    zero_kernel<<<(B_ * H_ * D_ * D_ + 1023) / 1024, 1024>>>(kv, B_ * H_ * D_ * D_);
    zero_kernel<<<(B_ * H_ * D_ + 1023) / 1024, 1024>>>(ksum, B_ * H_ * D_);

    // 3) kv & ksum reductions
    kv_kernel<<<dim3(B_ * H_, KV_SPLIT), 256>>>(phik, v, kv, ksum);

    // 4) attention output
    attn_out_kernel<<<dim3(B_ * H_, NTOK / 8), 256>>>(phiq, kv, ksum, attn);

    // 5) layernorm -> fp16
    ln_kernel<<<M_, 256>>>(attn, norm_g, norm_b, lh);

    // 6) out = ln @ proj_w^T + proj_b
    mma_gemm_proj<<<dim3(C_ / BN, M_ / BM), 256, SMEM_GEMM>>>(
        lh, pw, out, C_, proj_b);
}